// round 2
// baseline (speedup 1.0000x reference)
#include <cuda_runtime.h>
#include <cstdint>
#include <cstddef>

// SubgraphConvolution: out[i] = feat[i] + (mean_k feat[nbr[i,k]]) @ W^T + b
// N=100000, D=128, K=32. Indices are INT32 (jax x64 disabled).
// L2-resident gather (51MB feats fits in 126MB L2) -> L2-BW-bound design.

#define THREADS 256
#define NODES_PER_BLOCK 64
#define GROUPS (NODES_PER_BLOCK / 8)

static constexpr int D = 128;
static constexpr int KDEG = 32;
// Wt layout: for each j2 in [0,64): row of 256 floats holding pairs
//   Wt[j2*STRIDE + 2*d + 0] = W[d][2*j2], Wt[j2*STRIDE + 2*d + 1] = W[d][2*j2+1]
// STRIDE=258 (pad 2) -> conflict-free transposing stores and float2 loads.
static constexpr int WT_STRIDE = 258;
static constexpr int WT_FLOATS = 64 * WT_STRIDE;              // 16512
static constexpr int SMEM_FLOATS = WT_FLOATS + 8 * 128 + 128; // + agg[8][128] + b[128]
static constexpr int SMEM_BYTES = SMEM_FLOATS * 4;            // 70656 B -> 3 CTAs/SM

__global__ __launch_bounds__(THREADS, 3)
void subgconv_kernel(const float* __restrict__ feat,
                     const int* __restrict__ nbr,
                     const int* __restrict__ nidx,
                     const float* __restrict__ W,
                     const float* __restrict__ bias,
                     float* __restrict__ out,
                     int N)
{
    extern __shared__ float smem[];
    float* Wt    = smem;
    float* agg_s = smem + WT_FLOATS;     // 8 rows x 128 floats
    float* b_s   = agg_s + 8 * 128;      // 128 floats

    const int tid = threadIdx.x;

    // --- One-time per block: load W transposed + j-paired into smem ---
    for (int idx = tid; idx < D * D; idx += THREADS) {
        int d = idx >> 7;
        int j = idx & 127;
        Wt[(j >> 1) * WT_STRIDE + 2 * d + (j & 1)] = W[idx];
    }
    if (tid < D) b_s[tid] = bias[tid];

    const int lane = tid & 31;
    const int w    = tid >> 5;           // warp id 0..7
    const int blockBase = blockIdx.x * NODES_PER_BLOCK;
    const float4* f4 = (const float4*)feat;

    const int d    = tid & 127;
    const int half = tid >> 7;           // 0: nodes 0-3 of group, 1: nodes 4-7

    for (int g = 0; g < GROUPS; g++) {
        const int gbase = blockBase + g * 8;
        __syncthreads();   // agg buffer reuse barrier (also orders Wt/b on g==0)

        // ---- Phase A: warp w gathers & averages neighbors of node gbase+w ----
        {
            int node = gbase + w;
            if (node < N) {
                float4 acc = make_float4(0.f, 0.f, 0.f, 0.f);
                const int* np = nbr + (size_t)node * KDEG;
                #pragma unroll 8
                for (int k = 0; k < KDEG; k++) {
                    int idx = np[k];                            // uniform per warp
                    float4 v = f4[(size_t)idx * 32 + lane];     // coalesced 512B row
                    acc.x += v.x; acc.y += v.y; acc.z += v.z; acc.w += v.w;
                }
                const float s = 1.0f / 32.0f;
                ((float4*)(agg_s + w * 128))[lane] =
                    make_float4(acc.x * s, acc.y * s, acc.z * s, acc.w * s);
            }
        }
        __syncthreads();

        // ---- Phase B: packed-f32x2 dot products: out_d = sum_j W[d][j]*agg[m][j] ----
        {
            const float* am = agg_s + half * 4 * 128;   // my 4 nodes' agg rows
            unsigned long long a0 = 0ull, a1 = 0ull, a2 = 0ull, a3 = 0ull;
            #pragma unroll 4
            for (int j2 = 0; j2 < 64; j2++) {
                unsigned long long wv =
                    *(const unsigned long long*)(Wt + j2 * WT_STRIDE + 2 * d);
                unsigned long long g0 = *(const unsigned long long*)(am +         2 * j2);
                unsigned long long g1 = *(const unsigned long long*)(am + 128 +   2 * j2);
                unsigned long long g2 = *(const unsigned long long*)(am + 256 +   2 * j2);
                unsigned long long g3 = *(const unsigned long long*)(am + 384 +   2 * j2);
                asm("fma.rn.f32x2 %0, %1, %2, %3;" : "=l"(a0) : "l"(wv), "l"(g0), "l"(a0));
                asm("fma.rn.f32x2 %0, %1, %2, %3;" : "=l"(a1) : "l"(wv), "l"(g1), "l"(a1));
                asm("fma.rn.f32x2 %0, %1, %2, %3;" : "=l"(a2) : "l"(wv), "l"(g2), "l"(a2));
                asm("fma.rn.f32x2 %0, %1, %2, %3;" : "=l"(a3) : "l"(wv), "l"(g3), "l"(a3));
            }
            float res[4];
            { float2 t = *(float2*)&a0; res[0] = t.x + t.y; }
            { float2 t = *(float2*)&a1; res[1] = t.x + t.y; }
            { float2 t = *(float2*)&a2; res[2] = t.x + t.y; }
            { float2 t = *(float2*)&a3; res[3] = t.x + t.y; }

            const float bd = b_s[d];
            #pragma unroll
            for (int mm = 0; mm < 4; mm++) {
                int nodem = gbase + half * 4 + mm;
                if (nodem < N) {
                    int r = nidx[nodem];
                    out[(size_t)nodem * D + d] =
                        feat[(size_t)r * D + d] + bd + res[mm];
                }
            }
        }
        __syncthreads();
    }
}

extern "C" void kernel_launch(void* const* d_in, const int* in_sizes, int n_in,
                              void* d_out, int out_size)
{
    const float* feat = (const float*)d_in[0];
    const int*   nbr  = (const int*)d_in[1];
    const int*   nidx = (const int*)d_in[2];
    const float* W    = (const float*)d_in[3];
    const float* bias = (const float*)d_in[4];
    float*       out  = (float*)d_out;

    const int N = in_sizes[2];

    cudaFuncSetAttribute(subgconv_kernel,
                         cudaFuncAttributeMaxDynamicSharedMemorySize, SMEM_BYTES);

    const int grid = (N + NODES_PER_BLOCK - 1) / NODES_PER_BLOCK;
    subgconv_kernel<<<grid, THREADS, SMEM_BYTES>>>(feat, nbr, nidx, W, bias, out, N);
}

// round 3
// speedup vs baseline: 1.0943x; 1.0943x over previous
#include <cuda_runtime.h>
#include <cstddef>

// out[i] = feat[i] + (mean_k feat[nbr[i,k]]) @ W^T + b
// N=100000, D=128, K=32, int32 indices. L2-resident gather; phase-B is a
// register-blocked smem GEMM (8d x 4n tiles, f32x2 FMAs over d-pairs).

#define THREADS 256
static constexpr int D     = 128;
static constexpr int KDEG  = 32;
static constexpr int GRP   = 64;    // nodes per group
static constexpr int NPB   = 128;   // nodes per block (2 groups)
static constexpr int NGRP  = NPB / GRP;

static constexpr int WJ_STRIDE  = 132;                // pad: conflict-free reads, 4-way-only transpose writes
static constexpr int WJ_FLOATS  = 128 * WJ_STRIDE;    // Wj[j][d] = W[d][j]
static constexpr int AGG_STRIDE = 132;
static constexpr int AGG_FLOATS = GRP * AGG_STRIDE;
static constexpr int SMEM_BYTES = (WJ_FLOATS + AGG_FLOATS + 128) * 4;  // 101,888 B -> 2 CTAs/SM

__global__ __launch_bounds__(THREADS, 2)
void subgconv_kernel(const float* __restrict__ feat,
                     const int* __restrict__ nbr,
                     const int* __restrict__ nidx,
                     const float* __restrict__ W,
                     const float* __restrict__ bias,
                     float* __restrict__ out,
                     int N)
{
    extern __shared__ float smem[];
    float* Wj  = smem;                  // [128][WJ_STRIDE]
    float* agg = smem + WJ_FLOATS;      // [GRP][AGG_STRIDE]
    float* b_s = agg + AGG_FLOATS;      // [128]

    const int tid  = threadIdx.x;
    const int lane = tid & 31;
    const int w    = tid >> 5;          // warp 0..7
    const int db   = tid & 15;          // d-block: dims [8db, 8db+8)
    const int nb   = tid >> 4;          // n-block: nodes [4nb, 4nb+4) of group

    // --- One-time: W transposed into smem (coalesced LDG, 4-way-conflict STS) ---
    for (int idx = tid; idx < D * D; idx += THREADS) {
        int d = idx >> 7, j = idx & 127;
        Wj[j * WJ_STRIDE + d] = W[idx];
    }
    if (tid < D) b_s[tid] = bias[tid];

    const int blockBase = blockIdx.x * NPB;
    const float4* f4 = (const float4*)feat;

    for (int g = 0; g < NGRP; g++) {
        const int gbase = blockBase + g * GRP;
        __syncthreads();   // agg reuse barrier (orders Wj/b on first pass too)

        // ---- Phase A: warp w gathers+averages 8 nodes (pairs for MLP~8) ----
        #pragma unroll
        for (int nn = 0; nn < 8; nn += 2) {
            int n0 = gbase + w * 8 + nn;
            int n1 = n0 + 1;
            bool v0 = n0 < N, v1 = n1 < N;
            const int4* np0 = (const int4*)(nbr + (size_t)(v0 ? n0 : 0) * KDEG);
            const int4* np1 = (const int4*)(nbr + (size_t)(v1 ? n1 : 0) * KDEG);
            float4 a0 = make_float4(0.f,0.f,0.f,0.f);
            float4 a1 = make_float4(0.f,0.f,0.f,0.f);
            #pragma unroll
            for (int k4 = 0; k4 < 8; k4++) {
                int4 i0 = np0[k4];
                int4 i1 = np1[k4];
                float4 t;
                t = f4[(size_t)i0.x*32 + lane]; a0.x+=t.x; a0.y+=t.y; a0.z+=t.z; a0.w+=t.w;
                t = f4[(size_t)i1.x*32 + lane]; a1.x+=t.x; a1.y+=t.y; a1.z+=t.z; a1.w+=t.w;
                t = f4[(size_t)i0.y*32 + lane]; a0.x+=t.x; a0.y+=t.y; a0.z+=t.z; a0.w+=t.w;
                t = f4[(size_t)i1.y*32 + lane]; a1.x+=t.x; a1.y+=t.y; a1.z+=t.z; a1.w+=t.w;
                t = f4[(size_t)i0.z*32 + lane]; a0.x+=t.x; a0.y+=t.y; a0.z+=t.z; a0.w+=t.w;
                t = f4[(size_t)i1.z*32 + lane]; a1.x+=t.x; a1.y+=t.y; a1.z+=t.z; a1.w+=t.w;
                t = f4[(size_t)i0.w*32 + lane]; a0.x+=t.x; a0.y+=t.y; a0.z+=t.z; a0.w+=t.w;
                t = f4[(size_t)i1.w*32 + lane]; a1.x+=t.x; a1.y+=t.y; a1.z+=t.z; a1.w+=t.w;
            }
            const float s = 1.0f / 32.0f;
            if (v0) *(float4*)&agg[(w*8+nn  )*AGG_STRIDE + 4*lane] =
                make_float4(a0.x*s, a0.y*s, a0.z*s, a0.w*s);
            if (v1) *(float4*)&agg[(w*8+nn+1)*AGG_STRIDE + 4*lane] =
                make_float4(a1.x*s, a1.y*s, a1.z*s, a1.w*s);
        }
        __syncthreads();

        // ---- Phase B: 8d x 4n register tile, f32x2 FMAs over d-pairs ----
        {
            unsigned long long acc[4][4];   // [d-pair 0..3][node 0..3]
            #pragma unroll
            for (int p = 0; p < 4; p++)
                #pragma unroll
                for (int nn = 0; nn < 4; nn++) acc[p][nn] = 0ull;

            const float* aggb = agg + (nb * 4) * AGG_STRIDE;
            const float* wrow = Wj + db * 8;

            #pragma unroll 2
            for (int j = 0; j < 128; j++) {
                float4 wA = *(const float4*)(wrow + j * WJ_STRIDE);
                float4 wB = *(const float4*)(wrow + j * WJ_STRIDE + 4);
                unsigned long long wp0 = *(unsigned long long*)&wA.x;
                unsigned long long wp1 = *(unsigned long long*)&wA.z;
                unsigned long long wp2 = *(unsigned long long*)&wB.x;
                unsigned long long wp3 = *(unsigned long long*)&wB.z;
                #pragma unroll
                for (int nn = 0; nn < 4; nn++) {
                    float a = aggb[nn * AGG_STRIDE + j];
                    unsigned long long ad;
                    asm("mov.b64 %0, {%1, %1};" : "=l"(ad) : "f"(a));
                    asm("fma.rn.f32x2 %0, %1, %2, %3;" : "=l"(acc[0][nn]) : "l"(wp0), "l"(ad), "l"(acc[0][nn]));
                    asm("fma.rn.f32x2 %0, %1, %2, %3;" : "=l"(acc[1][nn]) : "l"(wp1), "l"(ad), "l"(acc[1][nn]));
                    asm("fma.rn.f32x2 %0, %1, %2, %3;" : "=l"(acc[2][nn]) : "l"(wp2), "l"(ad), "l"(acc[2][nn]));
                    asm("fma.rn.f32x2 %0, %1, %2, %3;" : "=l"(acc[3][nn]) : "l"(wp3), "l"(ad), "l"(acc[3][nn]));
                }
            }

            float4 bA = *(const float4*)&b_s[db * 8];
            float4 bB = *(const float4*)&b_s[db * 8 + 4];

            #pragma unroll
            for (int nn = 0; nn < 4; nn++) {
                int node = gbase + nb * 4 + nn;
                if (node < N) {
                    int r = nidx[node];
                    const float* fr = feat + (size_t)r * D + db * 8;
                    float4 fA = *(const float4*)(fr);
                    float4 fB = *(const float4*)(fr + 4);
                    float2 p0 = *(float2*)&acc[0][nn];
                    float2 p1 = *(float2*)&acc[1][nn];
                    float2 p2 = *(float2*)&acc[2][nn];
                    float2 p3 = *(float2*)&acc[3][nn];
                    float4 oA = make_float4(p0.x + fA.x + bA.x, p0.y + fA.y + bA.y,
                                            p1.x + fA.z + bA.z, p1.y + fA.w + bA.w);
                    float4 oB = make_float4(p2.x + fB.x + bB.x, p2.y + fB.y + bB.y,
                                            p3.x + fB.z + bB.z, p3.y + fB.w + bB.w);
                    float* op = out + (size_t)node * D + db * 8;
                    *(float4*)(op)     = oA;
                    *(float4*)(op + 4) = oB;
                }
            }
        }
        __syncthreads();
    }
}

extern "C" void kernel_launch(void* const* d_in, const int* in_sizes, int n_in,
                              void* d_out, int out_size)
{
    const float* feat = (const float*)d_in[0];
    const int*   nbr  = (const int*)d_in[1];
    const int*   nidx = (const int*)d_in[2];
    const float* W    = (const float*)d_in[3];
    const float* bias = (const float*)d_in[4];
    float*       out  = (float*)d_out;

    const int N = in_sizes[2];

    cudaFuncSetAttribute(subgconv_kernel,
                         cudaFuncAttributeMaxDynamicSharedMemorySize, SMEM_BYTES);

    const int grid = (N + NPB - 1) / NPB;
    subgconv_kernel<<<grid, THREADS, SMEM_BYTES>>>(feat, nbr, nidx, W, bias, out, N);
}

// round 5
// speedup vs baseline: 1.2334x; 1.1271x over previous
#include <cuda_runtime.h>
#include <cstddef>

// out[i] = feat[i] + (mean_k feat[nbr[i,k]]) @ W^T + b
// N=100000, D=128, K=32, int32 indices. L2-resident gather.
// LDG.64 gather; phase-B GEMM with lane-distinct contiguous W LDS.128
// (stride 132 -> 16B aligned) + broadcast agg float4.

#define THREADS 256
static constexpr int D     = 128;
static constexpr int KDEG  = 32;
static constexpr int GRP   = 64;     // nodes per group
static constexpr int NPB   = 128;    // nodes per block (2 groups)

static constexpr int WJ_STRIDE  = 132;               // 16B-aligned rows (4-way STS conflict, one-time)
static constexpr int WJ_FLOATS  = 128 * WJ_STRIDE;   // Wj[j][d] = W[d][j]
static constexpr int AGG_STRIDE = 132;
static constexpr int AGG_FLOATS = GRP * AGG_STRIDE;
static constexpr int SMEM_BYTES = (WJ_FLOATS + AGG_FLOATS + 128) * 4;  // 101,888 B -> 2 CTAs/SM

__global__ __launch_bounds__(THREADS, 2)
void subgconv_kernel(const float* __restrict__ feat,
                     const int* __restrict__ nbr,
                     const int* __restrict__ nidx,
                     const float* __restrict__ W,
                     const float* __restrict__ bias,
                     float* __restrict__ out,
                     int N)
{
    extern __shared__ float smem[];
    float* Wj  = smem;                  // [128][WJ_STRIDE]
    float* agg = smem + WJ_FLOATS;      // [GRP][AGG_STRIDE]
    float* b_s = agg + AGG_FLOATS;      // [128]

    const int tid  = threadIdx.x;
    const int lane = tid & 31;
    const int w    = tid >> 5;          // warp 0..7

    // --- One-time: W transpose into smem (coalesced LDG; 4-way-conflict STS, amortized) ---
    for (int base = tid; base < D * D; base += THREADS) {
        int d = base >> 7, j = base & 127;
        Wj[j * WJ_STRIDE + d] = W[d * D + j];
    }
    if (tid < D) b_s[tid] = bias[tid];

    const int blockBase = blockIdx.x * NPB;
    const float2* f2 = (const float2*)feat;

    for (int g = 0; g < 2; g++) {
        const int gbase = blockBase + g * GRP;
        __syncthreads();   // agg reuse barrier; also orders Wj/b_s before phase B

        // ---- Phase A: warp w gathers+averages 8 nodes (pairs for MLP) ----
        #pragma unroll
        for (int nn = 0; nn < 8; nn += 2) {
            int n0 = gbase + w * 8 + nn;
            int n1 = n0 + 1;
            bool v0 = n0 < N, v1 = n1 < N;
            const int4* np0 = (const int4*)(nbr + (size_t)(v0 ? n0 : 0) * KDEG);
            const int4* np1 = (const int4*)(nbr + (size_t)(v1 ? n1 : 0) * KDEG);
            float2 a0l = make_float2(0.f,0.f), a0h = make_float2(0.f,0.f);
            float2 a1l = make_float2(0.f,0.f), a1h = make_float2(0.f,0.f);
            #pragma unroll 4
            for (int k4 = 0; k4 < 8; k4++) {
                int4 i0 = np0[k4];
                int4 i1 = np1[k4];
                float2 t;
                size_t b;
                b = (size_t)i0.x*64 + lane; t = f2[b]; a0l.x+=t.x; a0l.y+=t.y; t = f2[b+32]; a0h.x+=t.x; a0h.y+=t.y;
                b = (size_t)i1.x*64 + lane; t = f2[b]; a1l.x+=t.x; a1l.y+=t.y; t = f2[b+32]; a1h.x+=t.x; a1h.y+=t.y;
                b = (size_t)i0.y*64 + lane; t = f2[b]; a0l.x+=t.x; a0l.y+=t.y; t = f2[b+32]; a0h.x+=t.x; a0h.y+=t.y;
                b = (size_t)i1.y*64 + lane; t = f2[b]; a1l.x+=t.x; a1l.y+=t.y; t = f2[b+32]; a1h.x+=t.x; a1h.y+=t.y;
                b = (size_t)i0.z*64 + lane; t = f2[b]; a0l.x+=t.x; a0l.y+=t.y; t = f2[b+32]; a0h.x+=t.x; a0h.y+=t.y;
                b = (size_t)i1.z*64 + lane; t = f2[b]; a1l.x+=t.x; a1l.y+=t.y; t = f2[b+32]; a1h.x+=t.x; a1h.y+=t.y;
                b = (size_t)i0.w*64 + lane; t = f2[b]; a0l.x+=t.x; a0l.y+=t.y; t = f2[b+32]; a0h.x+=t.x; a0h.y+=t.y;
                b = (size_t)i1.w*64 + lane; t = f2[b]; a1l.x+=t.x; a1l.y+=t.y; t = f2[b+32]; a1h.x+=t.x; a1h.y+=t.y;
            }
            const float s = 1.0f / 32.0f;
            if (v0) {
                float* r = agg + (w*8+nn) * AGG_STRIDE;
                *(float2*)(r + 2*lane)      = make_float2(a0l.x*s, a0l.y*s);
                *(float2*)(r + 64 + 2*lane) = make_float2(a0h.x*s, a0h.y*s);
            }
            if (v1) {
                float* r = agg + (w*8+nn+1) * AGG_STRIDE;
                *(float2*)(r + 2*lane)      = make_float2(a1l.x*s, a1l.y*s);
                *(float2*)(r + 64 + 2*lane) = make_float2(a1h.x*s, a1h.y*s);
            }
        }
        __syncthreads();

        // ---- Phase B: warps 0-3; warp w computes 128d x 16n (nodes w*16..+16).
        // Thread tile 4d x 16n, d = 4*lane..4*lane+4, f32x2 accs over d-pairs. ----
        if (w < 4) {
            unsigned long long acc0[16], acc1[16];
            #pragma unroll
            for (int n = 0; n < 16; n++) { acc0[n] = 0ull; acc1[n] = 0ull; }

            const float* aggb = agg + (w * 16) * AGG_STRIDE;
            const float* wcol = Wj + lane * 4;

            #pragma unroll 1
            for (int j4 = 0; j4 < 32; j4++) {
                // 4 W quads: lane-distinct contiguous 16B over 512B rows -> 4 clean wf each
                float4 wv0 = *(const float4*)(wcol + (4*j4+0) * WJ_STRIDE);
                float4 wv1 = *(const float4*)(wcol + (4*j4+1) * WJ_STRIDE);
                float4 wv2 = *(const float4*)(wcol + (4*j4+2) * WJ_STRIDE);
                float4 wv3 = *(const float4*)(wcol + (4*j4+3) * WJ_STRIDE);
                unsigned long long w0a = *(unsigned long long*)&wv0.x, w0b = *(unsigned long long*)&wv0.z;
                unsigned long long w1a = *(unsigned long long*)&wv1.x, w1b = *(unsigned long long*)&wv1.z;
                unsigned long long w2a = *(unsigned long long*)&wv2.x, w2b = *(unsigned long long*)&wv2.z;
                unsigned long long w3a = *(unsigned long long*)&wv3.x, w3b = *(unsigned long long*)&wv3.z;

                #pragma unroll
                for (int n = 0; n < 16; n++) {
                    float4 av = *(const float4*)(aggb + n * AGG_STRIDE + 4*j4);  // broadcast, 1 wf
                    unsigned long long ad;
                    asm("mov.b64 %0, {%1, %1};" : "=l"(ad) : "f"(av.x));
                    asm("fma.rn.f32x2 %0, %1, %2, %3;" : "=l"(acc0[n]) : "l"(w0a), "l"(ad), "l"(acc0[n]));
                    asm("fma.rn.f32x2 %0, %1, %2, %3;" : "=l"(acc1[n]) : "l"(w0b), "l"(ad), "l"(acc1[n]));
                    asm("mov.b64 %0, {%1, %1};" : "=l"(ad) : "f"(av.y));
                    asm("fma.rn.f32x2 %0, %1, %2, %3;" : "=l"(acc0[n]) : "l"(w1a), "l"(ad), "l"(acc0[n]));
                    asm("fma.rn.f32x2 %0, %1, %2, %3;" : "=l"(acc1[n]) : "l"(w1b), "l"(ad), "l"(acc1[n]));
                    asm("mov.b64 %0, {%1, %1};" : "=l"(ad) : "f"(av.z));
                    asm("fma.rn.f32x2 %0, %1, %2, %3;" : "=l"(acc0[n]) : "l"(w2a), "l"(ad), "l"(acc0[n]));
                    asm("fma.rn.f32x2 %0, %1, %2, %3;" : "=l"(acc1[n]) : "l"(w2b), "l"(ad), "l"(acc1[n]));
                    asm("mov.b64 %0, {%1, %1};" : "=l"(ad) : "f"(av.w));
                    asm("fma.rn.f32x2 %0, %1, %2, %3;" : "=l"(acc0[n]) : "l"(w3a), "l"(ad), "l"(acc0[n]));
                    asm("fma.rn.f32x2 %0, %1, %2, %3;" : "=l"(acc1[n]) : "l"(w3b), "l"(ad), "l"(acc1[n]));
                }
            }

            // Epilogue: out[node][4l..4l+4) = acc + feat[nidx[node]] + b
            float4 bv = *(const float4*)&b_s[lane * 4];
            const int nbase = gbase + w * 16;
            #pragma unroll
            for (int n = 0; n < 16; n++) {
                int node = nbase + n;
                if (node < N) {
                    int r = nidx[node];
                    float4 fv = ((const float4*)feat)[(size_t)r * 32 + lane];
                    float2 p0 = *(float2*)&acc0[n];
                    float2 p1 = *(float2*)&acc1[n];
                    float4 o = make_float4(p0.x + fv.x + bv.x, p0.y + fv.y + bv.y,
                                           p1.x + fv.z + bv.z, p1.y + fv.w + bv.w);
                    ((float4*)out)[(size_t)node * 32 + lane] = o;
                }
            }
        }
        __syncthreads();
    }
}

extern "C" void kernel_launch(void* const* d_in, const int* in_sizes, int n_in,
                              void* d_out, int out_size)
{
    const float* feat = (const float*)d_in[0];
    const int*   nbr  = (const int*)d_in[1];
    const int*   nidx = (const int*)d_in[2];
    const float* W    = (const float*)d_in[3];
    const float* bias = (const float*)d_in[4];
    float*       out  = (float*)d_out;

    const int N = in_sizes[2];

    cudaFuncSetAttribute(subgconv_kernel,
                         cudaFuncAttributeMaxDynamicSharedMemorySize, SMEM_BYTES);

    const int grid = (N + NPB - 1) / NPB;
    subgconv_kernel<<<grid, THREADS, SMEM_BYTES>>>(feat, nbr, nidx, W, bias, out, N);
}

// round 6
// speedup vs baseline: 1.6315x; 1.3227x over previous
#include <cuda_runtime.h>
#include <cstddef>

// out[i] = feat[i] + (mean_k feat[nbr[i,k]]) @ W^T + b
// N=100000, D=128, K=32, int32 indices. L2-resident gather.
// R6: W transposed into a __device__ global by a pre-kernel; main kernel smem
// holds only agg (34KB) -> 4 CTAs/SM, all 8 warps gather AND compute.

#define THREADS 256
static constexpr int D     = 128;
static constexpr int KDEG  = 32;
static constexpr int NPB   = 64;     // nodes per block

static constexpr int AGG_STRIDE = 132;                 // float4-aligned rows (528B)
static constexpr int AGG_FLOATS = NPB * AGG_STRIDE;
static constexpr int SMEM_BYTES = (AGG_FLOATS + 128) * 4;   // 34,304 B -> 4 CTAs/SM

__device__ __align__(16) float Wt_g[D * D];   // Wt_g[j][d] = W[d][j]

// --- Pre-kernel: 32x32 smem-tiled transpose, both sides coalesced ---
__global__ void transpose_kernel(const float* __restrict__ W)
{
    __shared__ float tile[32][33];
    int bx = blockIdx.x & 3, by = blockIdx.x >> 2;    // 16 blocks of 32x32
    int x  = bx * 32 + threadIdx.x;
    int y0 = by * 32 + threadIdx.y;
    #pragma unroll
    for (int r = 0; r < 32; r += 8)
        tile[threadIdx.y + r][threadIdx.x] = W[(y0 + r) * D + x];
    __syncthreads();
    int xo = by * 32 + threadIdx.x;
    int yo = bx * 32 + threadIdx.y;
    #pragma unroll
    for (int r = 0; r < 32; r += 8)
        Wt_g[(yo + r) * D + xo] = tile[threadIdx.x][threadIdx.y + r];
}

__global__ __launch_bounds__(THREADS, 4)
void subgconv_kernel(const float* __restrict__ feat,
                     const int* __restrict__ nbr,
                     const int* __restrict__ nidx,
                     const float* __restrict__ bias,
                     float* __restrict__ out,
                     int N)
{
    extern __shared__ float smem[];
    float* agg = smem;                   // [NPB][AGG_STRIDE]
    float* b_s = smem + AGG_FLOATS;      // [128]

    const int tid  = threadIdx.x;
    const int lane = tid & 31;
    const int w    = tid >> 5;           // warp 0..7

    if (tid < D) b_s[tid] = bias[tid];

    const int gbase = blockIdx.x * NPB;
    const float2* f2 = (const float2*)feat;

    // ---- Phase A: warp w gathers+averages nodes gbase + w*8 .. +8 (pairs for MLP) ----
    #pragma unroll
    for (int nn = 0; nn < 8; nn += 2) {
        int n0 = gbase + w * 8 + nn;
        int n1 = n0 + 1;
        bool v0 = n0 < N, v1 = n1 < N;
        const int4* np0 = (const int4*)(nbr + (size_t)(v0 ? n0 : 0) * KDEG);
        const int4* np1 = (const int4*)(nbr + (size_t)(v1 ? n1 : 0) * KDEG);
        float2 a0l = make_float2(0.f,0.f), a0h = make_float2(0.f,0.f);
        float2 a1l = make_float2(0.f,0.f), a1h = make_float2(0.f,0.f);
        #pragma unroll 4
        for (int k4 = 0; k4 < 8; k4++) {
            int4 i0 = np0[k4];
            int4 i1 = np1[k4];
            float2 t;
            size_t b;
            b = (size_t)i0.x*64 + lane; t = f2[b]; a0l.x+=t.x; a0l.y+=t.y; t = f2[b+32]; a0h.x+=t.x; a0h.y+=t.y;
            b = (size_t)i1.x*64 + lane; t = f2[b]; a1l.x+=t.x; a1l.y+=t.y; t = f2[b+32]; a1h.x+=t.x; a1h.y+=t.y;
            b = (size_t)i0.y*64 + lane; t = f2[b]; a0l.x+=t.x; a0l.y+=t.y; t = f2[b+32]; a0h.x+=t.x; a0h.y+=t.y;
            b = (size_t)i1.y*64 + lane; t = f2[b]; a1l.x+=t.x; a1l.y+=t.y; t = f2[b+32]; a1h.x+=t.x; a1h.y+=t.y;
            b = (size_t)i0.z*64 + lane; t = f2[b]; a0l.x+=t.x; a0l.y+=t.y; t = f2[b+32]; a0h.x+=t.x; a0h.y+=t.y;
            b = (size_t)i1.z*64 + lane; t = f2[b]; a1l.x+=t.x; a1l.y+=t.y; t = f2[b+32]; a1h.x+=t.x; a1h.y+=t.y;
            b = (size_t)i0.w*64 + lane; t = f2[b]; a0l.x+=t.x; a0l.y+=t.y; t = f2[b+32]; a0h.x+=t.x; a0h.y+=t.y;
            b = (size_t)i1.w*64 + lane; t = f2[b]; a1l.x+=t.x; a1l.y+=t.y; t = f2[b+32]; a1h.x+=t.x; a1h.y+=t.y;
        }
        const float s = 1.0f / 32.0f;
        if (v0) {
            float* r = agg + (w*8+nn) * AGG_STRIDE;
            *(float2*)(r + 2*lane)      = make_float2(a0l.x*s, a0l.y*s);
            *(float2*)(r + 64 + 2*lane) = make_float2(a0h.x*s, a0h.y*s);
        }
        if (v1) {
            float* r = agg + (w*8+nn+1) * AGG_STRIDE;
            *(float2*)(r + 2*lane)      = make_float2(a1l.x*s, a1l.y*s);
            *(float2*)(r + 64 + 2*lane) = make_float2(a1h.x*s, a1h.y*s);
        }
    }
    __syncthreads();

    // ---- Phase B: all 8 warps; warp w computes 128d x 8n (nodes w*8..+8).
    // Thread tile 4d x 8n, d = 4*lane..+4; W rows from L1-resident Wt_g. ----
    {
        unsigned long long acc0[8], acc1[8];
        #pragma unroll
        for (int n = 0; n < 8; n++) { acc0[n] = 0ull; acc1[n] = 0ull; }

        const float* aggb = agg + (w * 8) * AGG_STRIDE;
        const float* wcol = Wt_g + lane * 4;

        #pragma unroll 1
        for (int j4 = 0; j4 < 32; j4++) {
            float4 wv0 = *(const float4*)(wcol + (4*j4+0) * D);
            float4 wv1 = *(const float4*)(wcol + (4*j4+1) * D);
            float4 wv2 = *(const float4*)(wcol + (4*j4+2) * D);
            float4 wv3 = *(const float4*)(wcol + (4*j4+3) * D);
            unsigned long long w0a = *(unsigned long long*)&wv0.x, w0b = *(unsigned long long*)&wv0.z;
            unsigned long long w1a = *(unsigned long long*)&wv1.x, w1b = *(unsigned long long*)&wv1.z;
            unsigned long long w2a = *(unsigned long long*)&wv2.x, w2b = *(unsigned long long*)&wv2.z;
            unsigned long long w3a = *(unsigned long long*)&wv3.x, w3b = *(unsigned long long*)&wv3.z;

            #pragma unroll
            for (int n = 0; n < 8; n++) {
                float4 av = *(const float4*)(aggb + n * AGG_STRIDE + 4*j4);  // broadcast, 1 wf
                unsigned long long ad;
                asm("mov.b64 %0, {%1, %1};" : "=l"(ad) : "f"(av.x));
                asm("fma.rn.f32x2 %0, %1, %2, %3;" : "=l"(acc0[n]) : "l"(w0a), "l"(ad), "l"(acc0[n]));
                asm("fma.rn.f32x2 %0, %1, %2, %3;" : "=l"(acc1[n]) : "l"(w0b), "l"(ad), "l"(acc1[n]));
                asm("mov.b64 %0, {%1, %1};" : "=l"(ad) : "f"(av.y));
                asm("fma.rn.f32x2 %0, %1, %2, %3;" : "=l"(acc0[n]) : "l"(w1a), "l"(ad), "l"(acc0[n]));
                asm("fma.rn.f32x2 %0, %1, %2, %3;" : "=l"(acc1[n]) : "l"(w1b), "l"(ad), "l"(acc1[n]));
                asm("mov.b64 %0, {%1, %1};" : "=l"(ad) : "f"(av.z));
                asm("fma.rn.f32x2 %0, %1, %2, %3;" : "=l"(acc0[n]) : "l"(w2a), "l"(ad), "l"(acc0[n]));
                asm("fma.rn.f32x2 %0, %1, %2, %3;" : "=l"(acc1[n]) : "l"(w2b), "l"(ad), "l"(acc1[n]));
                asm("mov.b64 %0, {%1, %1};" : "=l"(ad) : "f"(av.w));
                asm("fma.rn.f32x2 %0, %1, %2, %3;" : "=l"(acc0[n]) : "l"(w3a), "l"(ad), "l"(acc0[n]));
                asm("fma.rn.f32x2 %0, %1, %2, %3;" : "=l"(acc1[n]) : "l"(w3b), "l"(ad), "l"(acc1[n]));
            }
        }

        // Epilogue: out[node][4l..4l+4) = acc + feat[nidx[node]] + b
        float4 bv = *(const float4*)&b_s[lane * 4];
        const int nbase = gbase + w * 8;
        #pragma unroll
        for (int n = 0; n < 8; n++) {
            int node = nbase + n;
            if (node < N) {
                int r = nidx[node];
                float4 fv = ((const float4*)feat)[(size_t)r * 32 + lane];
                float2 p0 = *(float2*)&acc0[n];
                float2 p1 = *(float2*)&acc1[n];
                float4 o = make_float4(p0.x + fv.x + bv.x, p0.y + fv.y + bv.y,
                                       p1.x + fv.z + bv.z, p1.y + fv.w + bv.w);
                ((float4*)out)[(size_t)node * 32 + lane] = o;
            }
        }
    }
}

extern "C" void kernel_launch(void* const* d_in, const int* in_sizes, int n_in,
                              void* d_out, int out_size)
{
    const float* feat = (const float*)d_in[0];
    const int*   nbr  = (const int*)d_in[1];
    const int*   nidx = (const int*)d_in[2];
    const float* W    = (const float*)d_in[3];
    const float* bias = (const float*)d_in[4];
    float*       out  = (float*)d_out;

    const int N = in_sizes[2];

    // 1) transpose W into Wt_g (both sides coalesced, ~few us)
    transpose_kernel<<<16, dim3(32, 8)>>>(W);

    // 2) main kernel
    cudaFuncSetAttribute(subgconv_kernel,
                         cudaFuncAttributeMaxDynamicSharedMemorySize, SMEM_BYTES);
    const int grid = (N + NPB - 1) / NPB;
    subgconv_kernel<<<grid, THREADS, SMEM_BYTES>>>(feat, nbr, nidx, bias, out, N);
}